// round 2
// baseline (speedup 1.0000x reference)
#include <cuda_runtime.h>
#include <math.h>

#define BATCH 8
#define SEQ   2048
#define DIN   1024
#define DHEAD 128
#define NROWS (BATCH * SEQ)

typedef unsigned long long u64;

// packed fp32x2 helpers (sm_100+ PTX; identical rounding to scalar fmaf)
__device__ __forceinline__ u64 FMA2(u64 a, u64 b, u64 c) {
    u64 d; asm("fma.rn.f32x2 %0, %1, %2, %3;" : "=l"(d) : "l"(a), "l"(b), "l"(c));
    return d;
}
__device__ __forceinline__ u64 MUL2(u64 a, u64 b) {
    u64 d; asm("mul.rn.f32x2 %0, %1, %2;" : "=l"(d) : "l"(a), "l"(b));
    return d;
}
__device__ __forceinline__ u64 PACK2(float x, float y) {
    u64 r; asm("mov.b64 %0, {%1, %2};" : "=l"(r) : "f"(x), "f"(y));
    return r;
}
__device__ __forceinline__ float LO2(u64 v) { return __uint_as_float((unsigned)v); }
__device__ __forceinline__ float HI2(u64 v) { return __uint_as_float((unsigned)(v >> 32)); }

// scratch for Q/K/V projections (8 MB each)
__device__ float g_Q[NROWS * DHEAD];
__device__ float g_K[NROWS * DHEAD];
__device__ float g_V[NROWS * DHEAD];

// ---------------------------------------------------------------------------
// Projection: out = X @ W + b. blockIdx.y selects {Wq,Wk,Wv}.
// Tile 64 rows x 128 cols, 256 threads, k-step 32.
// W tile transposed in smem so fp32x2 pairs are contiguous along k.
// ---------------------------------------------------------------------------
#define WT_STRIDE 34   // 34 mod 32 == 2 -> 2-way LDS conflicts, 8B aligned

__global__ __launch_bounds__(256) void proj_kernel(
    const float* __restrict__ X,
    const float* __restrict__ Wq, const float* __restrict__ bq,
    const float* __restrict__ Wk, const float* __restrict__ bk,
    const float* __restrict__ Wv, const float* __restrict__ bv)
{
    const float* W; const float* bias; float* out;
    if (blockIdx.y == 0)      { W = Wq; bias = bq; out = g_Q; }
    else if (blockIdx.y == 1) { W = Wk; bias = bk; out = g_K; }
    else                      { W = Wv; bias = bv; out = g_V; }

    __shared__ float Xs[64][32];
    __shared__ float Wt[128][WT_STRIDE];   // transposed: Wt[col][k]

    const int tid = threadIdx.x;
    const int tx = tid & 31;          // output cols: tx + 32*j
    const int ty = tid >> 5;          // 8 output rows each
    const int row0 = blockIdx.x * 64;

    u64 acc2[8][4];
    #pragma unroll
    for (int i = 0; i < 8; i++)
        #pragma unroll
        for (int j = 0; j < 4; j++) acc2[i][j] = 0ull;

    for (int k = 0; k < DIN; k += 32) {
        // load X tile 64x32 (512 float4, 2 per thread)
        #pragma unroll
        for (int l = 0; l < 2; l++) {
            int e = tid + l * 256;
            int r = e >> 3, c4 = (e & 7) * 4;
            *(float4*)&Xs[r][c4] =
                *(const float4*)&X[(size_t)(row0 + r) * DIN + k + c4];
        }
        // load W tile 32x128 and transpose into Wt
        #pragma unroll
        for (int l = 0; l < 4; l++) {
            int e = tid + l * 256;
            int r = e >> 5, c4 = (e & 31) * 4;
            float4 w = *(const float4*)&W[(size_t)(k + r) * DHEAD + c4];
            Wt[c4 + 0][r] = w.x;
            Wt[c4 + 1][r] = w.y;
            Wt[c4 + 2][r] = w.z;
            Wt[c4 + 3][r] = w.w;
        }
        __syncthreads();

        #pragma unroll
        for (int kk2 = 0; kk2 < 16; kk2++) {
            u64 bp[4];
            #pragma unroll
            for (int j = 0; j < 4; j++)
                bp[j] = *(const u64*)&Wt[tx + 32 * j][2 * kk2];
            #pragma unroll
            for (int i = 0; i < 8; i++) {
                u64 ap = *(const u64*)&Xs[ty * 8 + i][2 * kk2];
                #pragma unroll
                for (int j = 0; j < 4; j++)
                    acc2[i][j] = FMA2(ap, bp[j], acc2[i][j]);
            }
        }
        __syncthreads();
    }

    #pragma unroll
    for (int j = 0; j < 4; j++) {
        int col = tx + 32 * j;
        float bb = bias[col];
        #pragma unroll
        for (int i = 0; i < 8; i++) {
            out[(size_t)(row0 + ty * 8 + i) * DHEAD + col] =
                LO2(acc2[i][j]) + HI2(acc2[i][j]) + bb;
        }
    }
}

// ---------------------------------------------------------------------------
// Flash-style causal attention, fp32x2 inner loops.
// Block: one (batch, 64-query tile). 256 threads.
// V stored transposed in smem so PV pairs along t are contiguous.
// Reference quirks honored: causal zeros -> -inf, plus (w == 0) -> -inf.
// ---------------------------------------------------------------------------
#define QS_STRIDE 132   // even (8B pair alignment); Q reads are broadcast
#define KS_STRIDE 132   // strided-j mapping -> lane spacing 132 mod 32 = 4 -> 2-way
#define VT_STRIDE 66    // 66 mod 32 = 2 -> 2-way
#define PS_STRIDE 66

#define SMEM_FLOATS (64*QS_STRIDE + 64*KS_STRIDE + 128*VT_STRIDE + 64*PS_STRIDE + 192)

__global__ __launch_bounds__(256) void attn_kernel(
    const float* __restrict__ drop_mask, float* __restrict__ out)
{
    extern __shared__ float sm[];
    float* Qs      = sm;                          // [64][132]
    float* Ks      = Qs + 64 * QS_STRIDE;         // [64][132]
    float* Vt      = Ks + 64 * KS_STRIDE;         // [128][66]  (transposed V)
    float* Ps      = Vt + 128 * VT_STRIDE;        // [64][66]
    float* m_s     = Ps + 64 * PS_STRIDE;         // [64]
    float* l_s     = m_s + 64;                    // [64]
    float* scale_s = l_s + 64;                    // [64]

    const int tid = threadIdx.x;
    const int qt  = 31 - (int)blockIdx.x;         // big tiles first
    const int bb  = blockIdx.y;
    const int q0  = qt * 64;
    const size_t batch_off = (size_t)bb * SEQ * DHEAD;

    // S-compute layout: 16x16 threads; each owns 4 q rows x 4 k cols (cols strided by 16)
    const int tx4 = tid & 15;
    const int ty4 = tid >> 4;
    // PV/output layout: 8x32 threads; 8 rows x 4 cols (cols strided by 32)
    const int txo = tid & 31;
    const int tyo = tid >> 5;

    if (tid < 64) { m_s[tid] = -INFINITY; l_s[tid] = 0.f; }

    // load Q tile
    #pragma unroll
    for (int it = 0; it < 8; it++) {
        int idx = tid + it * 256;
        int t = idx >> 5, c4 = (idx & 31) * 4;
        *(float4*)&Qs[t * QS_STRIDE + c4] =
            *(const float4*)&g_Q[batch_off + (size_t)(q0 + t) * DHEAD + c4];
    }

    u64 acc2[8][4];
    #pragma unroll
    for (int i = 0; i < 8; i++)
        #pragma unroll
        for (int j = 0; j < 4; j++) acc2[i][j] = 0ull;

    for (int kt = 0; kt <= qt; kt++) {
        const int k0 = kt * 64;

        // load K tile (row-major, pairs along d) and V tile (transposed)
        #pragma unroll
        for (int it = 0; it < 8; it++) {
            int idx = tid + it * 256;
            int t = idx >> 5, c4 = (idx & 31) * 4;
            *(float4*)&Ks[t * KS_STRIDE + c4] =
                *(const float4*)&g_K[batch_off + (size_t)(k0 + t) * DHEAD + c4];
            float4 vv = *(const float4*)&g_V[batch_off + (size_t)(k0 + t) * DHEAD + c4];
            Vt[(c4 + 0) * VT_STRIDE + t] = vv.x;
            Vt[(c4 + 1) * VT_STRIDE + t] = vv.y;
            Vt[(c4 + 2) * VT_STRIDE + t] = vv.z;
            Vt[(c4 + 3) * VT_STRIDE + t] = vv.w;
        }
        __syncthreads();

        // ---- S = Q @ K^T (64x64), fp32x2 pairs along d ----
        u64 s2[4][4];
        #pragma unroll
        for (int i = 0; i < 4; i++)
            #pragma unroll
            for (int j = 0; j < 4; j++) s2[i][j] = 0ull;

        #pragma unroll 8
        for (int d2 = 0; d2 < DHEAD / 2; d2++) {
            u64 bp[4];
            #pragma unroll
            for (int j = 0; j < 4; j++)
                bp[j] = *(const u64*)&Ks[(tx4 + 16 * j) * KS_STRIDE + 2 * d2];
            #pragma unroll
            for (int i = 0; i < 4; i++) {
                u64 ap = *(const u64*)&Qs[(ty4 * 4 + i) * QS_STRIDE + 2 * d2];
                #pragma unroll
                for (int j = 0; j < 4; j++)
                    s2[i][j] = FMA2(ap, bp[j], s2[i][j]);
            }
        }

        float s[4][4];
        #pragma unroll
        for (int i = 0; i < 4; i++)
            #pragma unroll
            for (int j = 0; j < 4; j++)
                s[i][j] = LO2(s2[i][j]) + HI2(s2[i][j]);

        // ---- masking: causal -inf above diagonal, and exact-zero -> -inf ----
        #pragma unroll
        for (int i = 0; i < 4; i++) {
            int qrow = q0 + ty4 * 4 + i;
            #pragma unroll
            for (int j = 0; j < 4; j++) {
                int kcol = k0 + tx4 + 16 * j;
                if (kcol > qrow || s[i][j] == 0.0f) s[i][j] = -INFINITY;
            }
        }

        // ---- online softmax update ----
        float mt[4];
        #pragma unroll
        for (int i = 0; i < 4; i++)
            mt[i] = fmaxf(fmaxf(s[i][0], s[i][1]), fmaxf(s[i][2], s[i][3]));
        #pragma unroll
        for (int off = 1; off < 16; off <<= 1)
            #pragma unroll
            for (int i = 0; i < 4; i++)
                mt[i] = fmaxf(mt[i], __shfl_xor_sync(0xffffffffu, mt[i], off));

        float m_old[4], m_new[4];
        #pragma unroll
        for (int i = 0; i < 4; i++) {
            m_old[i] = m_s[ty4 * 4 + i];
            m_new[i] = fmaxf(m_old[i], mt[i]);
        }

        float p[4][4], rs[4];
        #pragma unroll
        for (int i = 0; i < 4; i++) {
            #pragma unroll
            for (int j = 0; j < 4; j++) p[i][j] = __expf(s[i][j] - m_new[i]);
            rs[i] = (p[i][0] + p[i][1]) + (p[i][2] + p[i][3]);
        }
        #pragma unroll
        for (int off = 1; off < 16; off <<= 1)
            #pragma unroll
            for (int i = 0; i < 4; i++)
                rs[i] += __shfl_xor_sync(0xffffffffu, rs[i], off);

        __syncwarp();
        if (tx4 == 0) {
            #pragma unroll
            for (int i = 0; i < 4; i++) {
                int r = ty4 * 4 + i;
                float sc = __expf(m_old[i] - m_new[i]);
                scale_s[r] = sc;
                l_s[r]     = l_s[r] * sc + rs[i];
                m_s[r]     = m_new[i];
            }
        }

        // ---- apply dropout mask, stage P into smem ----
        #pragma unroll
        for (int i = 0; i < 4; i++) {
            int qrow = q0 + ty4 * 4 + i;
            const float* mrow = &drop_mask[((size_t)bb * SEQ + qrow) * SEQ + k0];
            #pragma unroll
            for (int j = 0; j < 4; j++) {
                Ps[(ty4 * 4 + i) * PS_STRIDE + tx4 + 16 * j] =
                    p[i][j] * mrow[tx4 + 16 * j];
            }
        }
        __syncthreads();

        // ---- rescale accumulators, O += P @ V (fp32x2 pairs along t) ----
        #pragma unroll
        for (int i = 0; i < 8; i++) {
            float scl = scale_s[tyo * 8 + i];
            u64 sp = PACK2(scl, scl);
            #pragma unroll
            for (int j = 0; j < 4; j++) acc2[i][j] = MUL2(acc2[i][j], sp);
        }

        #pragma unroll 4
        for (int t2 = 0; t2 < 32; t2++) {
            u64 vp[4];
            #pragma unroll
            for (int j = 0; j < 4; j++)
                vp[j] = *(const u64*)&Vt[(txo + 32 * j) * VT_STRIDE + 2 * t2];
            #pragma unroll
            for (int i = 0; i < 8; i++) {
                u64 pp = *(const u64*)&Ps[(tyo * 8 + i) * PS_STRIDE + 2 * t2];
                #pragma unroll
                for (int j = 0; j < 4; j++)
                    acc2[i][j] = FMA2(pp, vp[j], acc2[i][j]);
            }
        }
        __syncthreads();
    }

    // ---- finalize ----
    #pragma unroll
    for (int i = 0; i < 8; i++) {
        float inv = 1.0f / l_s[tyo * 8 + i];
        #pragma unroll
        for (int j = 0; j < 4; j++) {
            int col = txo + 32 * j;
            out[batch_off + (size_t)(q0 + tyo * 8 + i) * DHEAD + col] =
                (LO2(acc2[i][j]) + HI2(acc2[i][j])) * inv;
        }
    }
}

// ---------------------------------------------------------------------------
extern "C" void kernel_launch(void* const* d_in, const int* in_sizes, int n_in,
                              void* d_out, int out_size)
{
    const float* X  = (const float*)d_in[0];
    const float* Wq = (const float*)d_in[1];
    const float* bq = (const float*)d_in[2];
    const float* Wk = (const float*)d_in[3];
    const float* bk = (const float*)d_in[4];
    const float* Wv = (const float*)d_in[5];
    const float* bv = (const float*)d_in[6];
    const float* dm = (const float*)d_in[7];
    float* out = (float*)d_out;

    dim3 g1(NROWS / 64, 3);
    proj_kernel<<<g1, 256>>>(X, Wq, bq, Wk, bk, Wv, bv);

    const size_t smem_bytes = (size_t)SMEM_FLOATS * sizeof(float);  // ~116 KB
    cudaFuncSetAttribute(attn_kernel,
                         cudaFuncAttributeMaxDynamicSharedMemorySize,
                         (int)smem_bytes);
    dim3 g2(32, BATCH);
    attn_kernel<<<g2, 256, smem_bytes>>>(dm, out);
}

// round 3
// speedup vs baseline: 2.6886x; 2.6886x over previous
#include <cuda_runtime.h>
#include <math.h>

#define BATCH 8
#define SEQ   2048
#define DIN   1024
#define DHEAD 128
#define NROWS (BATCH * SEQ)

typedef unsigned int  u32;
typedef unsigned short u16;

// ---------------------------------------------------------------------------
// split-bf16 global scratch
// ---------------------------------------------------------------------------
__device__ __align__(16) u16 g_Xh[NROWS * DIN];
__device__ __align__(16) u16 g_Xl[NROWS * DIN];
__device__ __align__(16) u16 g_Wh[3 * DIN * DHEAD];
__device__ __align__(16) u16 g_Wl[3 * DIN * DHEAD];
__device__ __align__(16) u16 g_Qh[NROWS * DHEAD];
__device__ __align__(16) u16 g_Ql[NROWS * DHEAD];
__device__ __align__(16) u16 g_Kh[NROWS * DHEAD];
__device__ __align__(16) u16 g_Kl[NROWS * DHEAD];
__device__ __align__(16) u16 g_Vh[NROWS * DHEAD];
__device__ __align__(16) u16 g_Vl[NROWS * DHEAD];

// ---------------------------------------------------------------------------
// helpers
// ---------------------------------------------------------------------------
__device__ __forceinline__ u32 cvt2(float lo, float hi) {  // pack bf16(lo)|bf16(hi)<<16
    u32 r; asm("cvt.rn.bf16x2.f32 %0, %1, %2;" : "=r"(r) : "f"(hi), "f"(lo));
    return r;
}
__device__ __forceinline__ float bflo(u32 v) { return __uint_as_float(v << 16); }
__device__ __forceinline__ float bfhi(u32 v) { return __uint_as_float(v & 0xffff0000u); }

__device__ __forceinline__ u32 s2u(const void* p) {
    u32 a;
    asm("{.reg .u64 t; cvta.to.shared.u64 t, %1; cvt.u32.u64 %0, t;}" : "=r"(a) : "l"(p));
    return a;
}
__device__ __forceinline__ void ldm_x4(u32& r0, u32& r1, u32& r2, u32& r3, u32 a) {
    asm volatile("ldmatrix.sync.aligned.m8n8.x4.shared.b16 {%0,%1,%2,%3},[%4];"
                 : "=r"(r0), "=r"(r1), "=r"(r2), "=r"(r3) : "r"(a));
}
__device__ __forceinline__ void ldm_x4t(u32& r0, u32& r1, u32& r2, u32& r3, u32 a) {
    asm volatile("ldmatrix.sync.aligned.m8n8.x4.trans.shared.b16 {%0,%1,%2,%3},[%4];"
                 : "=r"(r0), "=r"(r1), "=r"(r2), "=r"(r3) : "r"(a));
}
__device__ __forceinline__ void mma16816(float c[4], u32 a0, u32 a1, u32 a2, u32 a3,
                                         u32 b0, u32 b1) {
    asm volatile(
        "mma.sync.aligned.m16n8k16.row.col.f32.bf16.bf16.f32 "
        "{%0,%1,%2,%3},{%4,%5,%6,%7},{%8,%9},{%0,%1,%2,%3};"
        : "+f"(c[0]), "+f"(c[1]), "+f"(c[2]), "+f"(c[3])
        : "r"(a0), "r"(a1), "r"(a2), "r"(a3), "r"(b0), "r"(b1));
}

// ---------------------------------------------------------------------------
// split pass: fp32 -> (hi, lo) bf16
// ---------------------------------------------------------------------------
__global__ void split_x_kernel(const float* __restrict__ X)
{
    const int N4 = NROWS * DIN / 4;
    for (int i = blockIdx.x * blockDim.x + threadIdx.x; i < N4;
         i += gridDim.x * blockDim.x) {
        float4 v = ((const float4*)X)[i];
        u32 h0 = cvt2(v.x, v.y), h1 = cvt2(v.z, v.w);
        u32 l0 = cvt2(v.x - bflo(h0), v.y - bfhi(h0));
        u32 l1 = cvt2(v.z - bflo(h1), v.w - bfhi(h1));
        ((uint2*)g_Xh)[i] = make_uint2(h0, h1);
        ((uint2*)g_Xl)[i] = make_uint2(l0, l1);
    }
}

__global__ void split_w_kernel(const float* __restrict__ Wq,
                               const float* __restrict__ Wk,
                               const float* __restrict__ Wv)
{
    const int per = DIN * DHEAD / 4;          // 32768 float4 per matrix
    int i = blockIdx.x * blockDim.x + threadIdx.x;
    if (i >= 3 * per) return;
    const float* src = (i < per) ? Wq : (i < 2 * per) ? Wk : Wv;
    float4 v = ((const float4*)src)[i % per];
    u32 h0 = cvt2(v.x, v.y), h1 = cvt2(v.z, v.w);
    u32 l0 = cvt2(v.x - bflo(h0), v.y - bfhi(h0));
    u32 l1 = cvt2(v.z - bflo(h1), v.w - bfhi(h1));
    ((uint2*)g_Wh)[i] = make_uint2(h0, h1);
    ((uint2*)g_Wl)[i] = make_uint2(l0, l1);
}

// ---------------------------------------------------------------------------
// Projection GEMM: [16384 x 1024] @ [1024 x 128] + b, 3x, bf16 split MMA.
// CTA: 128 rows x 128 cols, 256 threads (8 warps, each m16 x n128).
// Writes split-bf16 Q/K/V directly.
// ---------------------------------------------------------------------------
#define PX_STR 40     // ushort stride of X tiles (80B: ldmatrix conflict-free)
#define PW_STR 136    // ushort stride of W tiles (272B)

__global__ __launch_bounds__(256, 2) void proj_mma_kernel(
    const float* __restrict__ bq, const float* __restrict__ bk,
    const float* __restrict__ bv)
{
    __shared__ __align__(16) u16 Xh_s[128 * PX_STR];
    __shared__ __align__(16) u16 Xl_s[128 * PX_STR];
    __shared__ __align__(16) u16 Wh_s[32 * PW_STR];
    __shared__ __align__(16) u16 Wl_s[32 * PW_STR];

    const int tid = threadIdx.x, lane = tid & 31, wid = tid >> 5;
    const int sel = blockIdx.y;
    const u16* Wh = g_Wh + sel * (DIN * DHEAD);
    const u16* Wl = g_Wl + sel * (DIN * DHEAD);
    const float* bias = (sel == 0) ? bq : (sel == 1) ? bk : bv;
    u16* outh = (sel == 0) ? g_Qh : (sel == 1) ? g_Kh : g_Vh;
    u16* outl = (sel == 0) ? g_Ql : (sel == 1) ? g_Kl : g_Vl;

    float c[16][4];
    #pragma unroll
    for (int i = 0; i < 16; i++)
        #pragma unroll
        for (int j = 0; j < 4; j++) c[i][j] = 0.f;

    const u32 xh_b = s2u(Xh_s), xl_b = s2u(Xl_s);
    const u32 wh_b = s2u(Wh_s), wl_b = s2u(Wl_s);

    // ldmatrix lane->address offsets
    const u32 a_off = (u32)(wid * 16 + (lane & 15)) * (PX_STR * 2) +
                      ((lane & 16) ? 16u : 0u);
    const u32 b_off = (u32)((lane & 7) + ((lane & 8) ? 8 : 0)) * (PW_STR * 2) +
                      ((lane & 16) ? 16u : 0u);

    const size_t xrow0 = (size_t)blockIdx.x * 128;

    for (int ks = 0; ks < DIN / 32; ks++) {
        __syncthreads();
        // stage X tile [128][32] and W tile [32][128] (hi & lo)
        #pragma unroll
        for (int l2 = 0; l2 < 2; l2++) {
            int e = tid + l2 * 256;
            int r = e >> 2, cu = e & 3;
            *(uint4*)&Xh_s[r * PX_STR + cu * 8] =
                *(const uint4*)&g_Xh[(xrow0 + r) * DIN + ks * 32 + cu * 8];
            *(uint4*)&Xl_s[r * PX_STR + cu * 8] =
                *(const uint4*)&g_Xl[(xrow0 + r) * DIN + ks * 32 + cu * 8];
            int r2 = e >> 4, cu2 = e & 15;
            *(uint4*)&Wh_s[r2 * PW_STR + cu2 * 8] =
                *(const uint4*)&Wh[(size_t)(ks * 32 + r2) * DHEAD + cu2 * 8];
            *(uint4*)&Wl_s[r2 * PW_STR + cu2 * 8] =
                *(const uint4*)&Wl[(size_t)(ks * 32 + r2) * DHEAD + cu2 * 8];
        }
        __syncthreads();

        #pragma unroll
        for (int kc = 0; kc < 2; kc++) {
            u32 ah0, ah1, ah2, ah3, al0, al1, al2, al3;
            ldm_x4(ah0, ah1, ah2, ah3, xh_b + a_off + kc * 32);
            ldm_x4(al0, al1, al2, al3, xl_b + a_off + kc * 32);
            #pragma unroll
            for (int ntp = 0; ntp < 8; ntp++) {
                u32 bh0, bh1, bh2, bh3, bl0, bl1, bl2, bl3;
                u32 boff2 = b_off + (u32)(kc * 16) * (PW_STR * 2) + ntp * 32;
                ldm_x4t(bh0, bh1, bh2, bh3, wh_b + boff2);
                ldm_x4t(bl0, bl1, bl2, bl3, wl_b + boff2);
                mma16816(c[2 * ntp], ah0, ah1, ah2, ah3, bh0, bh1);
                mma16816(c[2 * ntp], ah0, ah1, ah2, ah3, bl0, bl1);
                mma16816(c[2 * ntp], al0, al1, al2, al3, bh0, bh1);
                mma16816(c[2 * ntp + 1], ah0, ah1, ah2, ah3, bh2, bh3);
                mma16816(c[2 * ntp + 1], ah0, ah1, ah2, ah3, bl2, bl3);
                mma16816(c[2 * ntp + 1], al0, al1, al2, al3, bh2, bh3);
            }
        }
    }

    // epilogue: +bias, split to bf16 pairs, store
    const size_t r0 = xrow0 + wid * 16 + (lane >> 2);
    const size_t r1 = r0 + 8;
    #pragma unroll
    for (int nt = 0; nt < 16; nt++) {
        int col = nt * 8 + (lane & 3) * 2;
        float b0 = bias[col], b1 = bias[col + 1];
        float v00 = c[nt][0] + b0, v01 = c[nt][1] + b1;
        float v10 = c[nt][2] + b0, v11 = c[nt][3] + b1;
        u32 h0 = cvt2(v00, v01), l0 = cvt2(v00 - bflo(h0), v01 - bfhi(h0));
        u32 h1 = cvt2(v10, v11), l1 = cvt2(v10 - bflo(h1), v11 - bfhi(h1));
        *(u32*)&outh[r0 * DHEAD + col] = h0;
        *(u32*)&outl[r0 * DHEAD + col] = l0;
        *(u32*)&outh[r1 * DHEAD + col] = h1;
        *(u32*)&outl[r1 * DHEAD + col] = l1;
    }
}

// ---------------------------------------------------------------------------
// Flash attention, bf16 split MMA. CTA = (batch, q-tile pair {bx, 31-bx}).
// 128 threads (4 warps, each m16). K-tile 64. Reference quirks honored.
// ---------------------------------------------------------------------------
#define AS_STR 136   // ushort stride (272B rows): conflict-free ldmatrix
#define ATT_SMEM (6 * 64 * AS_STR * 2)   // 104448 bytes

__global__ __launch_bounds__(128, 2) void attn_mma_kernel(
    const float* __restrict__ dm, float* __restrict__ out)
{
    extern __shared__ __align__(16) u16 sm_[];
    u16* Qh_s = sm_;
    u16* Ql_s = Qh_s + 64 * AS_STR;
    u16* Kh_s = Ql_s + 64 * AS_STR;
    u16* Kl_s = Kh_s + 64 * AS_STR;
    u16* Vh_s = Kl_s + 64 * AS_STR;
    u16* Vl_s = Vh_s + 64 * AS_STR;

    const int tid = threadIdx.x, lane = tid & 31, wid = tid >> 5;
    const int b = blockIdx.y;
    const size_t brow = (size_t)b * SEQ;

    const u32 qh_b = s2u(Qh_s), ql_b = s2u(Ql_s);
    const u32 kh_b = s2u(Kh_s), kl_b = s2u(Kl_s);
    const u32 vh_b = s2u(Vh_s), vl_b = s2u(Vl_s);

    // ldmatrix lane->offset patterns
    const u32 a_off = (u32)(wid * 16 + (lane & 15)) * (AS_STR * 2) +
                      ((lane & 16) ? 16u : 0u);                      // A (plain)
    const u32 bk_off = (u32)((lane & 7) + ((lane & 16) ? 8 : 0)) * (AS_STR * 2) +
                       ((lane & 8) ? 16u : 0u);                      // B plain (K)
    const u32 bv_off = (u32)((lane & 7) + ((lane & 8) ? 8 : 0)) * (AS_STR * 2) +
                       ((lane & 16) ? 16u : 0u);                     // B trans (V)

    for (int half = 0; half < 2; half++) {
        const int qt = half == 0 ? (31 - (int)blockIdx.x) : (int)blockIdx.x;
        const int q0 = qt * 64;

        __syncthreads();
        // stage Q tile (hi & lo)
        #pragma unroll
        for (int l2 = 0; l2 < 8; l2++) {
            int e = tid + l2 * 128;
            int r = e >> 4, cu = e & 15;
            *(uint4*)&Qh_s[r * AS_STR + cu * 8] =
                *(const uint4*)&g_Qh[(brow + q0 + r) * DHEAD + cu * 8];
            *(uint4*)&Ql_s[r * AS_STR + cu * 8] =
                *(const uint4*)&g_Ql[(brow + q0 + r) * DHEAD + cu * 8];
        }

        float o[16][4];
        #pragma unroll
        for (int i = 0; i < 16; i++)
            #pragma unroll
            for (int j = 0; j < 4; j++) o[i][j] = 0.f;
        float m0 = -INFINITY, m1 = -INFINITY, l0 = 0.f, l1 = 0.f;

        const int rA = q0 + wid * 16 + (lane >> 2);
        const int rB = rA + 8;

        for (int kt = 0; kt <= qt; kt++) {
            const int k0 = kt * 64;
            __syncthreads();
            // stage K/V tiles (hi & lo)
            #pragma unroll
            for (int l2 = 0; l2 < 8; l2++) {
                int e = tid + l2 * 128;
                int r = e >> 4, cu = e & 15;
                size_t g = (brow + k0 + r) * DHEAD + cu * 8;
                int sidx = r * AS_STR + cu * 8;
                *(uint4*)&Kh_s[sidx] = *(const uint4*)&g_Kh[g];
                *(uint4*)&Kl_s[sidx] = *(const uint4*)&g_Kl[g];
                *(uint4*)&Vh_s[sidx] = *(const uint4*)&g_Vh[g];
                *(uint4*)&Vl_s[sidx] = *(const uint4*)&g_Vl[g];
            }
            __syncthreads();

            // ---- S = Q K^T (16 x 64 per warp) ----
            float s[8][4];
            #pragma unroll
            for (int i = 0; i < 8; i++)
                #pragma unroll
                for (int j = 0; j < 4; j++) s[i][j] = 0.f;

            #pragma unroll
            for (int kc = 0; kc < 8; kc++) {
                u32 ah0, ah1, ah2, ah3, al0, al1, al2, al3;
                ldm_x4(ah0, ah1, ah2, ah3, qh_b + a_off + kc * 32);
                ldm_x4(al0, al1, al2, al3, ql_b + a_off + kc * 32);
                #pragma unroll
                for (int ntp = 0; ntp < 4; ntp++) {
                    u32 bh0, bh1, bh2, bh3, bl0, bl1, bl2, bl3;
                    u32 off = bk_off + (u32)(ntp * 16) * (AS_STR * 2) + kc * 32;
                    ldm_x4(bh0, bh1, bh2, bh3, kh_b + off);
                    ldm_x4(bl0, bl1, bl2, bl3, kl_b + off);
                    mma16816(s[2 * ntp], ah0, ah1, ah2, ah3, bh0, bh1);
                    mma16816(s[2 * ntp], ah0, ah1, ah2, ah3, bl0, bl1);
                    mma16816(s[2 * ntp], al0, al1, al2, al3, bh0, bh1);
                    mma16816(s[2 * ntp + 1], ah0, ah1, ah2, ah3, bh2, bh3);
                    mma16816(s[2 * ntp + 1], ah0, ah1, ah2, ah3, bl2, bl3);
                    mma16816(s[2 * ntp + 1], al0, al1, al2, al3, bh2, bh3);
                }
            }

            // ---- masking + online softmax ----
            float mx0 = -INFINITY, mx1 = -INFINITY;
            #pragma unroll
            for (int nt = 0; nt < 8; nt++) {
                int kc0 = k0 + nt * 8 + (lane & 3) * 2;
                if (kc0     > rA || s[nt][0] == 0.f) s[nt][0] = -INFINITY;
                if (kc0 + 1 > rA || s[nt][1] == 0.f) s[nt][1] = -INFINITY;
                if (kc0     > rB || s[nt][2] == 0.f) s[nt][2] = -INFINITY;
                if (kc0 + 1 > rB || s[nt][3] == 0.f) s[nt][3] = -INFINITY;
                mx0 = fmaxf(mx0, fmaxf(s[nt][0], s[nt][1]));
                mx1 = fmaxf(mx1, fmaxf(s[nt][2], s[nt][3]));
            }
            mx0 = fmaxf(mx0, __shfl_xor_sync(0xffffffffu, mx0, 1));
            mx0 = fmaxf(mx0, __shfl_xor_sync(0xffffffffu, mx0, 2));
            mx1 = fmaxf(mx1, __shfl_xor_sync(0xffffffffu, mx1, 1));
            mx1 = fmaxf(mx1, __shfl_xor_sync(0xffffffffu, mx1, 2));

            float mn0 = fmaxf(m0, mx0), mn1 = fmaxf(m1, mx1);
            float sum0 = 0.f, sum1 = 0.f;
            #pragma unroll
            for (int nt = 0; nt < 8; nt++) {
                s[nt][0] = __expf(s[nt][0] - mn0);
                s[nt][1] = __expf(s[nt][1] - mn0);
                s[nt][2] = __expf(s[nt][2] - mn1);
                s[nt][3] = __expf(s[nt][3] - mn1);
                sum0 += s[nt][0] + s[nt][1];
                sum1 += s[nt][2] + s[nt][3];
            }
            sum0 += __shfl_xor_sync(0xffffffffu, sum0, 1);
            sum0 += __shfl_xor_sync(0xffffffffu, sum0, 2);
            sum1 += __shfl_xor_sync(0xffffffffu, sum1, 1);
            sum1 += __shfl_xor_sync(0xffffffffu, sum1, 2);

            float sc0 = __expf(m0 - mn0), sc1 = __expf(m1 - mn1);
            l0 = l0 * sc0 + sum0;  m0 = mn0;
            l1 = l1 * sc1 + sum1;  m1 = mn1;

            #pragma unroll
            for (int nt = 0; nt < 16; nt++) {
                o[nt][0] *= sc0; o[nt][1] *= sc0;
                o[nt][2] *= sc1; o[nt][3] *= sc1;
            }

            // ---- dropout mask ----
            #pragma unroll
            for (int nt = 0; nt < 8; nt++) {
                int kc0 = k0 + nt * 8 + (lane & 3) * 2;
                float2 ma = *(const float2*)&dm[(brow + rA) * SEQ + kc0];
                float2 mb = *(const float2*)&dm[(brow + rB) * SEQ + kc0];
                s[nt][0] *= ma.x; s[nt][1] *= ma.y;
                s[nt][2] *= mb.x; s[nt][3] *= mb.y;
            }

            // ---- O += P V : P splits in-register into A frags ----
            #pragma unroll
            for (int tc = 0; tc < 4; tc++) {
                u32 ph0 = cvt2(s[2 * tc][0], s[2 * tc][1]);
                u32 pl0 = cvt2(s[2 * tc][0] - bflo(ph0), s[2 * tc][1] - bfhi(ph0));
                u32 ph1 = cvt2(s[2 * tc][2], s[2 * tc][3]);
                u32 pl1 = cvt2(s[2 * tc][2] - bflo(ph1), s[2 * tc][3] - bfhi(ph1));
                u32 ph2 = cvt2(s[2 * tc + 1][0], s[2 * tc + 1][1]);
                u32 pl2 = cvt2(s[2 * tc + 1][0] - bflo(ph2), s[2 * tc + 1][1] - bfhi(ph2));
                u32 ph3 = cvt2(s[2 * tc + 1][2], s[2 * tc + 1][3]);
                u32 pl3 = cvt2(s[2 * tc + 1][2] - bflo(ph3), s[2 * tc + 1][3] - bfhi(ph3));
                #pragma unroll
                for (int ntp = 0; ntp < 8; ntp++) {
                    u32 bh0, bh1, bh2, bh3, bl0, bl1, bl2, bl3;
                    u32 off = bv_off + (u32)(tc * 16) * (AS_STR * 2) + ntp * 32;
                    ldm_x4t(bh0, bh1, bh2, bh3, vh_b + off);
                    ldm_x4t(bl0, bl1, bl2, bl3, vl_b + off);
                    mma16816(o[2 * ntp], ph0, ph1, ph2, ph3, bh0, bh1);
                    mma16816(o[2 * ntp], ph0, ph1, ph2, ph3, bl0, bl1);
                    mma16816(o[2 * ntp], pl0, pl1, pl2, pl3, bh0, bh1);
                    mma16816(o[2 * ntp + 1], ph0, ph1, ph2, ph3, bh2, bh3);
                    mma16816(o[2 * ntp + 1], ph0, ph1, ph2, ph3, bl2, bl3);
                    mma16816(o[2 * ntp + 1], pl0, pl1, pl2, pl3, bh2, bh3);
                }
            }
        } // kt

        // ---- finalize ----
        float inv0 = 1.0f / l0, inv1 = 1.0f / l1;
        #pragma unroll
        for (int nt = 0; nt < 16; nt++) {
            int col = nt * 8 + (lane & 3) * 2;
            float2 v0 = make_float2(o[nt][0] * inv0, o[nt][1] * inv0);
            float2 v1 = make_float2(o[nt][2] * inv1, o[nt][3] * inv1);
            *(float2*)&out[(brow + rA) * DHEAD + col] = v0;
            *(float2*)&out[(brow + rB) * DHEAD + col] = v1;
        }
    } // half
}

// ---------------------------------------------------------------------------
extern "C" void kernel_launch(void* const* d_in, const int* in_sizes, int n_in,
                              void* d_out, int out_size)
{
    const float* X  = (const float*)d_in[0];
    const float* Wq = (const float*)d_in[1];
    const float* bq = (const float*)d_in[2];
    const float* Wk = (const float*)d_in[3];
    const float* bk = (const float*)d_in[4];
    const float* Wv = (const float*)d_in[5];
    const float* bv = (const float*)d_in[6];
    const float* dm = (const float*)d_in[7];
    float* out = (float*)d_out;

    split_x_kernel<<<4096, 256>>>(X);
    split_w_kernel<<<384, 256>>>(Wq, Wk, Wv);

    dim3 gp(NROWS / 128, 3);
    proj_mma_kernel<<<gp, 256>>>(bq, bk, bv);

    cudaFuncSetAttribute(attn_mma_kernel,
                         cudaFuncAttributeMaxDynamicSharedMemorySize, ATT_SMEM);
    dim3 ga(16, BATCH);
    attn_mma_kernel<<<ga, 128, ATT_SMEM>>>(dm, out);
}